// round 6
// baseline (speedup 1.0000x reference)
#include <cuda_runtime.h>
#include <cuda_bf16.h>
#include <math.h>
#include <stdint.h>

#define T_TOK   4096
#define D_DIM   1024
#define H_DIM   512
#define HS_DIM  1024
#define E_NUM   32
#define TOPK    4
#define P_PAIRS (T_TOK*TOPK)
#define CAP     2048

#define BM 128
#define BK 32
#define STAGE_BYTES 32768
#define N_STAGE 3
#define DYN_SMEM (N_STAGE*STAGE_BYTES)

// ---------------- scratch ----------------
__device__ int   g_pair_e[P_PAIRS];
__device__ float g_pair_w[P_PAIRS];
__device__ int   g_pair_pos[P_PAIRS];          // e*CAP+pos if kept, -1 if dropped
__device__ int   g_slot_tok[E_NUM*CAP];
__device__ float g_slot_w[E_NUM*CAP];
__device__ int   g_count[E_NUM];
__device__ __align__(16) float g_pairbuf[(size_t)E_NUM*CAP*D_DIM];   // 268MB weighted expert outputs
__device__ __align__(16) __nv_bfloat16 g_hexp_hi[(size_t)E_NUM*CAP*H_DIM];
__device__ __align__(16) __nv_bfloat16 g_hexp_lo[(size_t)E_NUM*CAP*H_DIM];
__device__ __align__(16) __nv_bfloat16 g_hsh_hi[(size_t)T_TOK*HS_DIM];
__device__ __align__(16) __nv_bfloat16 g_hsh_lo[(size_t)T_TOK*HS_DIM];
// pre-split operands (native K-major layout)
__device__ __align__(16) __nv_bfloat16 g_Xh[(size_t)T_TOK*D_DIM],  g_Xl[(size_t)T_TOK*D_DIM];
__device__ __align__(16) __nv_bfloat16 g_W1h[(size_t)E_NUM*D_DIM*H_DIM], g_W1l[(size_t)E_NUM*D_DIM*H_DIM];
__device__ __align__(16) __nv_bfloat16 g_W3h[(size_t)E_NUM*D_DIM*H_DIM], g_W3l[(size_t)E_NUM*D_DIM*H_DIM];
__device__ __align__(16) __nv_bfloat16 g_W2h[(size_t)E_NUM*H_DIM*D_DIM], g_W2l[(size_t)E_NUM*H_DIM*D_DIM];
__device__ __align__(16) __nv_bfloat16 g_Ws1h[(size_t)D_DIM*HS_DIM], g_Ws1l[(size_t)D_DIM*HS_DIM];
__device__ __align__(16) __nv_bfloat16 g_Ws3h[(size_t)D_DIM*HS_DIM], g_Ws3l[(size_t)D_DIM*HS_DIM];
__device__ __align__(16) __nv_bfloat16 g_Ws2h[(size_t)HS_DIM*D_DIM], g_Ws2l[(size_t)HS_DIM*D_DIM];

// ---------------- helpers ----------------
__device__ __forceinline__ uint32_t smem_u32(const void* p) {
    return (uint32_t)__cvta_generic_to_shared(p);
}
__device__ __forceinline__ void cpa16(uint32_t dst, const void* src) {
    asm volatile("cp.async.cg.shared.global [%0], [%1], 16;" :: "r"(dst), "l"(src));
}
__device__ __forceinline__ void cpa16z(uint32_t dst, const void* src, bool valid) {
    int sz = valid ? 16 : 0;
    asm volatile("cp.async.cg.shared.global [%0], [%1], 16, %2;" :: "r"(dst), "l"(src), "r"(sz));
}
__device__ __forceinline__ void cpa_commit() { asm volatile("cp.async.commit_group;"); }
__device__ __forceinline__ void cpa_wait0()  { asm volatile("cp.async.wait_group 0;"); }
__device__ __forceinline__ void cpa_wait1()  { asm volatile("cp.async.wait_group 1;"); }
__device__ __forceinline__ void ldsm_x4(uint32_t* r, uint32_t a) {
    asm volatile("ldmatrix.sync.aligned.m8n8.x4.shared.b16 {%0,%1,%2,%3}, [%4];"
        : "=r"(r[0]), "=r"(r[1]), "=r"(r[2]), "=r"(r[3]) : "r"(a));
}
__device__ __forceinline__ void ldsm_x4_t(uint32_t* r, uint32_t a) {
    asm volatile("ldmatrix.sync.aligned.m8n8.x4.trans.shared.b16 {%0,%1,%2,%3}, [%4];"
        : "=r"(r[0]), "=r"(r[1]), "=r"(r[2]), "=r"(r[3]) : "r"(a));
}
__device__ __forceinline__ void mma16816(float* c, const uint32_t* a, const uint32_t* b) {
    asm volatile(
        "mma.sync.aligned.m16n8k16.row.col.f32.bf16.bf16.f32 "
        "{%0,%1,%2,%3}, {%4,%5,%6,%7}, {%8,%9}, {%0,%1,%2,%3};"
        : "+f"(c[0]), "+f"(c[1]), "+f"(c[2]), "+f"(c[3])
        : "r"(a[0]), "r"(a[1]), "r"(a[2]), "r"(a[3]), "r"(b[0]), "r"(b[1]));
}
__device__ __forceinline__ void split_bf16(float x, uint16_t& h, uint16_t& l) {
    __nv_bfloat16 hb = __float2bfloat16(x);
    float r = x - __bfloat162float(hb);
    __nv_bfloat16 lb = __float2bfloat16(r);
    h = __bfloat16_as_ushort(hb);
    l = __bfloat16_as_ushort(lb);
}
__device__ __forceinline__ void pack4(float4 v, uint2& hp, uint2& lp) {
    uint16_t hx,lx,hy,ly,hz,lz,hw,lw;
    split_bf16(v.x,hx,lx); split_bf16(v.y,hy,ly);
    split_bf16(v.z,hz,lz); split_bf16(v.w,hw,lw);
    hp = make_uint2((uint32_t)hx | ((uint32_t)hy<<16), (uint32_t)hz | ((uint32_t)hw<<16));
    lp = make_uint2((uint32_t)lx | ((uint32_t)ly<<16), (uint32_t)lz | ((uint32_t)lw<<16));
}
__device__ __forceinline__ uint32_t a_off(int r, int s) {          // 64B rows, s=16B chunk
    return (uint32_t)r*64u + (uint32_t)((s ^ ((r>>1)&3)) << 4);
}
__device__ __forceinline__ uint32_t b_off(int r, int s, int RB) {
    return (uint32_t)r*(uint32_t)RB + (uint32_t)((s ^ (r&7)) << 4);
}

// ---------------- split: fp32 -> (hi,lo) bf16 ----------------
__global__ __launch_bounds__(256)
void split_kernel(const float4* __restrict__ src, uint2* __restrict__ h,
                  uint2* __restrict__ l, int n4)
{
    for (int i = blockIdx.x*blockDim.x + threadIdx.x; i < n4; i += gridDim.x*blockDim.x) {
        uint2 hp, lp; pack4(src[i], hp, lp);
        h[i] = hp; l[i] = lp;
    }
}

// ---------------- gating ----------------
__global__ __launch_bounds__(256)
void gate_kernel(const float* __restrict__ X, const float* __restrict__ Wg)
{
    int warp = (blockIdx.x*blockDim.x + threadIdx.x) >> 5;
    int lane = threadIdx.x & 31;
    if (warp >= T_TOK) return;
    const float* xr = X + (size_t)warp * D_DIM;
    float xv[32];
    #pragma unroll
    for (int i = 0; i < 32; i++) xv[i] = xr[lane + 32*i];

    float mylogit = 0.f;
    #pragma unroll 1
    for (int e = 0; e < E_NUM; e++) {
        float d = 0.f;
        #pragma unroll
        for (int i = 0; i < 32; i++)
            d += xv[i] * Wg[(size_t)(lane + 32*i)*E_NUM + e];
        #pragma unroll
        for (int off = 16; off; off >>= 1) d += __shfl_xor_sync(0xffffffffu, d, off);
        if (lane == e) mylogit = d;
    }
    float m = mylogit;
    #pragma unroll
    for (int off = 16; off; off >>= 1) m = fmaxf(m, __shfl_xor_sync(0xffffffffu, m, off));
    float p = expf(mylogit - m);
    float s = p;
    #pragma unroll
    for (int off = 16; off; off >>= 1) s += __shfl_xor_sync(0xffffffffu, s, off);
    float prob = p / s;

    for (int k = 0; k < TOPK; k++) {
        float v = prob; int idx = lane;
        #pragma unroll
        for (int off = 16; off; off >>= 1) {
            float ov = __shfl_xor_sync(0xffffffffu, v, off);
            int   oi = __shfl_xor_sync(0xffffffffu, idx, off);
            if (ov > v || (ov == v && oi < idx)) { v = ov; idx = oi; }
        }
        if (lane == 0) {
            g_pair_e[warp*TOPK + k] = idx;
            g_pair_w[warp*TOPK + k] = v;
        }
        if (lane == idx) prob = -1.f;
    }
}

// ---------------- dispatch (also records pair -> pairbuf row) ----------------
__global__ __launch_bounds__(256)
void dispatch_kernel()
{
    int e = blockIdx.x;
    int tid = threadIdx.x;
    int lane = tid & 31, wid = tid >> 5;
    __shared__ int wtot[8];
    __shared__ int s_run;
    if (tid == 0) s_run = 0;
    __syncthreads();

    for (int base = 0; base < P_PAIRS; base += 256) {
        int p = base + tid;
        int flag = (g_pair_e[p] == e) ? 1 : 0;
        unsigned b = __ballot_sync(0xffffffffu, flag);
        int woff = __popc(b & ((1u << lane) - 1u));
        if (lane == 0) wtot[wid] = __popc(b);
        __syncthreads();
        int excl = 0, tot = 0;
        #pragma unroll
        for (int w = 0; w < 8; w++) { if (w < wid) excl += wtot[w]; tot += wtot[w]; }
        int pos = s_run + excl + woff;
        if (flag) {
            if (pos < CAP) {
                g_slot_tok[e*CAP + pos] = p >> 2;
                g_slot_w  [e*CAP + pos] = g_pair_w[p];
                g_pair_pos[p] = e*CAP + pos;
            } else {
                g_pair_pos[p] = -1;
            }
        }
        __syncthreads();
        if (tid == 0) s_run += tot;
        __syncthreads();
    }
    if (tid == 0) g_count[e] = min(s_run, CAP);
}

// ---------------- combine: out[t] += sum_k pairbuf[pos(t,k)] ----------------
__global__ __launch_bounds__(256)
void combine_kernel(float* __restrict__ out)
{
    int idx = blockIdx.x*blockDim.x + threadIdx.x;       // one float4 per thread
    int t  = idx >> 8;                                    // D_DIM/4 = 256
    int c4 = idx & 255;
    float4 acc = ((float4*)out)[idx];
    #pragma unroll
    for (int k = 0; k < TOPK; k++) {
        int pos = g_pair_pos[t*TOPK + k];
        if (pos >= 0) {
            float4 v = ((const float4*)g_pairbuf)[(size_t)pos*256 + c4];
            acc.x += v.x; acc.y += v.y; acc.z += v.z; acc.w += v.w;
        }
    }
    ((float4*)out)[idx] = acc;
}

// =====================================================================
// up: H = silu(X@W1) * (X@W3)  — mma.sync bf16 3-pass, 3-stage cp.async
// block 128x64, warps 2Mx4N, warp tile 64x16
// stage: Ah 0 Al 8192 B1h 16384 B1l 20480 B3h 24576 B3l 28672  (RB_B=128)
// =====================================================================
__global__ __launch_bounds__(256, 2)
void up_mma(int NN, int expert_mode)
{
    extern __shared__ char sm[];
    uint32_t sbase = smem_u32(sm);

    int e = blockIdx.z;
    int M_eff; const int* rows = nullptr;
    const __nv_bfloat16 *B1h_g, *B1l_g, *B3h_g, *B3l_g;
    __nv_bfloat16 *Hhi, *Hlo;
    if (expert_mode) {
        M_eff = g_count[e];
        rows  = g_slot_tok + e*CAP;
        size_t wo = (size_t)e*D_DIM*H_DIM;
        B1h_g = g_W1h + wo; B1l_g = g_W1l + wo;
        B3h_g = g_W3h + wo; B3l_g = g_W3l + wo;
        Hhi = g_hexp_hi + (size_t)e*CAP*NN;
        Hlo = g_hexp_lo + (size_t)e*CAP*NN;
    } else {
        M_eff = T_TOK;
        B1h_g = g_Ws1h; B1l_g = g_Ws1l; B3h_g = g_Ws3h; B3l_g = g_Ws3l;
        Hhi = g_hsh_hi; Hlo = g_hsh_lo;
    }
    int mbase = blockIdx.x * BM;
    if (mbase >= M_eff) return;
    int nbase = blockIdx.y * 64;
    const int KK = D_DIM;
    const int NT = KK / BK;

    int tid = threadIdx.x, lane = tid & 31, wid = tid >> 5;
    int wm = wid >> 2, wn = wid & 3;

    int ar0 = tid >> 2, as = tid & 3;
    bool avA[2]; const __nv_bfloat16 *XhP[2], *XlP[2];
    #pragma unroll
    for (int h = 0; h < 2; h++) {
        int slot = mbase + ar0 + h*64;
        avA[h] = slot < M_eff;
        int tok = avA[h] ? (rows ? rows[slot] : slot) : 0;
        XhP[h] = g_Xh + (size_t)tok*KK + as*8;
        XlP[h] = g_Xl + (size_t)tok*KK + as*8;
    }
    int brow = tid >> 3, bs = tid & 7;

    auto load_stage = [&](int s, int kt) {
        uint32_t st = sbase + (uint32_t)s*STAGE_BYTES;
        #pragma unroll
        for (int h = 0; h < 2; h++) {
            uint32_t d = a_off(ar0 + h*64, as);
            cpa16z(st + d,        XhP[h] + kt, avA[h]);
            cpa16z(st + 8192 + d, XlP[h] + kt, avA[h]);
        }
        uint32_t d = b_off(brow, bs, 128);
        size_t src = (size_t)(kt + brow)*NN + nbase + bs*8;
        cpa16(st + 16384 + d, B1h_g + src);
        cpa16(st + 20480 + d, B1l_g + src);
        cpa16(st + 24576 + d, B3h_g + src);
        cpa16(st + 28672 + d, B3l_g + src);
        cpa_commit();
    };

    float c1[4][2][4] = {}, c3[4][2][4] = {};

    load_stage(0, 0);
    load_stage(1, BK);
    for (int t = 0; t < NT; t++) {
        int s = t % N_STAGE;
        if (t < NT - 1) cpa_wait1(); else cpa_wait0();
        __syncthreads();
        if (t + 2 < NT) load_stage((t + 2) % N_STAGE, (t + 2) * BK);

        uint32_t st = sbase + (uint32_t)s*STAGE_BYTES;
        #pragma unroll
        for (int ks = 0; ks < 2; ks++) {
            int k0 = ks * 16;
            int rr = k0 + (lane & 7) + ((lane >> 3) & 1) * 8;
            int cc = wn*16 + (lane >> 4) * 8;
            uint32_t boff = b_off(rr, cc >> 3, 128);
            uint32_t b1h[4], b1l[4], b3h[4], b3l[4];
            ldsm_x4_t(b1h, st + 16384 + boff);
            ldsm_x4_t(b1l, st + 20480 + boff);
            ldsm_x4_t(b3h, st + 24576 + boff);
            ldsm_x4_t(b3l, st + 28672 + boff);
            #pragma unroll
            for (int mt = 0; mt < 4; mt++) {
                int r = wm*64 + mt*16 + (lane & 15);
                int sA = (k0 >> 3) + (lane >> 4);
                uint32_t aoff = a_off(r, sA);
                uint32_t ah[4], al[4];
                ldsm_x4(ah, st + aoff);
                ldsm_x4(al, st + 8192 + aoff);
                #pragma unroll
                for (int nt = 0; nt < 2; nt++) {
                    mma16816(c1[mt][nt], ah, &b1h[nt*2]);
                    mma16816(c1[mt][nt], ah, &b1l[nt*2]);
                    mma16816(c1[mt][nt], al, &b1h[nt*2]);
                    mma16816(c3[mt][nt], ah, &b3h[nt*2]);
                    mma16816(c3[mt][nt], ah, &b3l[nt*2]);
                    mma16816(c3[mt][nt], al, &b3h[nt*2]);
                }
            }
        }
    }

    int r0 = lane >> 2, cb = (lane & 3) * 2;
    #pragma unroll
    for (int mt = 0; mt < 4; mt++)
        #pragma unroll
        for (int nt = 0; nt < 2; nt++) {
            int n = nbase + wn*16 + nt*8 + cb;
            #pragma unroll
            for (int p = 0; p < 2; p++) {
                int m = mbase + wm*64 + mt*16 + r0 + p*8;
                if (m < M_eff) {
                    float g0 = c1[mt][nt][2*p+0], g1 = c1[mt][nt][2*p+1];
                    float v0 = g0 / (1.f + expf(-g0)) * c3[mt][nt][2*p+0];
                    float v1 = g1 / (1.f + expf(-g1)) * c3[mt][nt][2*p+1];
                    uint16_t h0,l0,h1,l1;
                    split_bf16(v0,h0,l0); split_bf16(v1,h1,l1);
                    *(uint32_t*)&Hhi[(size_t)m*NN + n] = (uint32_t)h0 | ((uint32_t)h1<<16);
                    *(uint32_t*)&Hlo[(size_t)m*NN + n] = (uint32_t)l0 | ((uint32_t)l1<<16);
                }
            }
        }
}

// =====================================================================
// down: mma.sync bf16 3-pass, 3-stage cp.async; block 128x128, warps 2Mx4N
// expert mode: weighted rows -> g_pairbuf (plain stores, no atomics)
// shared mode: dense store to out
// stage: Ah 0 Al 8192 Bh 16384 Bl 24576  (RB_B=256)
// =====================================================================
__global__ __launch_bounds__(256, 2)
void down_mma(int KK, int expert_mode, float* __restrict__ out)
{
    extern __shared__ char sm[];
    uint32_t sbase = smem_u32(sm);

    int e = blockIdx.z;
    int M_eff; const float* wv = nullptr;
    const __nv_bfloat16 *Ah_g, *Al_g, *Bh_g, *Bl_g;
    float* obase;
    if (expert_mode) {
        M_eff = g_count[e];
        wv    = g_slot_w  + e*CAP;
        size_t wo = (size_t)e*H_DIM*D_DIM;
        Bh_g = g_W2h + wo; Bl_g = g_W2l + wo;
        Ah_g = g_hexp_hi + (size_t)e*CAP*KK;
        Al_g = g_hexp_lo + (size_t)e*CAP*KK;
        obase = g_pairbuf + (size_t)e*CAP*D_DIM;
    } else {
        M_eff = T_TOK;
        Bh_g = g_Ws2h; Bl_g = g_Ws2l;
        Ah_g = g_hsh_hi; Al_g = g_hsh_lo;
        obase = out;
    }
    int mbase = blockIdx.x * BM;
    if (mbase >= M_eff) return;
    int nbase = blockIdx.y * 128;
    const int NT = KK / BK;

    int tid = threadIdx.x, lane = tid & 31, wid = tid >> 5;
    int wm = wid >> 2, wn = wid & 3;

    int ar0 = tid >> 2, as = tid & 3;
    bool avA[2]; const __nv_bfloat16 *AhP[2], *AlP[2];
    #pragma unroll
    for (int h = 0; h < 2; h++) {
        int slot = mbase + ar0 + h*64;
        avA[h] = slot < M_eff;
        int rr = avA[h] ? slot : mbase;
        AhP[h] = Ah_g + (size_t)rr*KK + as*8;
        AlP[h] = Al_g + (size_t)rr*KK + as*8;
    }
    int br0 = tid >> 4, bs0 = tid & 15;

    auto load_stage = [&](int s, int kt) {
        uint32_t st = sbase + (uint32_t)s*STAGE_BYTES;
        #pragma unroll
        for (int h = 0; h < 2; h++) {
            uint32_t d = a_off(ar0 + h*64, as);
            cpa16z(st + d,        AhP[h] + kt, avA[h]);
            cpa16z(st + 8192 + d, AlP[h] + kt, avA[h]);
        }
        #pragma unroll
        for (int h = 0; h < 2; h++) {
            int r = br0 + h*16;
            uint32_t d = b_off(r, bs0, 256);
            size_t src = (size_t)(kt + r)*D_DIM + nbase + bs0*8;
            cpa16(st + 16384 + d, Bh_g + src);
            cpa16(st + 24576 + d, Bl_g + src);
        }
        cpa_commit();
    };

    float c[4][4][4] = {};

    load_stage(0, 0);
    load_stage(1, BK);
    for (int t = 0; t < NT; t++) {
        int s = t % N_STAGE;
        if (t < NT - 1) cpa_wait1(); else cpa_wait0();
        __syncthreads();
        if (t + 2 < NT) load_stage((t + 2) % N_STAGE, (t + 2) * BK);

        uint32_t st = sbase + (uint32_t)s*STAGE_BYTES;
        #pragma unroll
        for (int ks = 0; ks < 2; ks++) {
            int k0 = ks * 16;
            int rr = k0 + (lane & 7) + ((lane >> 3) & 1) * 8;
            uint32_t bh[2][4], bl[2][4];
            #pragma unroll
            for (int h = 0; h < 2; h++) {
                int cc = wn*32 + h*16 + (lane >> 4) * 8;
                uint32_t boff = b_off(rr, cc >> 3, 256);
                ldsm_x4_t(bh[h], st + 16384 + boff);
                ldsm_x4_t(bl[h], st + 24576 + boff);
            }
            #pragma unroll
            for (int mt = 0; mt < 4; mt++) {
                int r = wm*64 + mt*16 + (lane & 15);
                int sA = (k0 >> 3) + (lane >> 4);
                uint32_t aoff = a_off(r, sA);
                uint32_t ah[4], al[4];
                ldsm_x4(ah, st + aoff);
                ldsm_x4(al, st + 8192 + aoff);
                #pragma unroll
                for (int nt = 0; nt < 4; nt++) {
                    mma16816(c[mt][nt], ah, &bh[nt>>1][(nt&1)*2]);
                    mma16816(c[mt][nt], ah, &bl[nt>>1][(nt&1)*2]);
                    mma16816(c[mt][nt], al, &bh[nt>>1][(nt&1)*2]);
                }
            }
        }
    }

    int r0 = lane >> 2, cb = (lane & 3) * 2;
    #pragma unroll
    for (int mt = 0; mt < 4; mt++) {
        #pragma unroll
        for (int p = 0; p < 2; p++) {
            int m = mbase + wm*64 + mt*16 + r0 + p*8;
            if (m >= M_eff) continue;
            float w = expert_mode ? wv[m] : 1.f;
            float* orow = obase + (size_t)m*D_DIM;
            #pragma unroll
            for (int nt = 0; nt < 4; nt++) {
                int n = nbase + wn*32 + nt*8 + cb;
                *(float2*)&orow[n] = make_float2(c[mt][nt][2*p+0] * w,
                                                 c[mt][nt][2*p+1] * w);
            }
        }
    }
}

// ---------------- host launcher ----------------
extern "C" void kernel_launch(void* const* d_in, const int* in_sizes, int n_in,
                              void* d_out, int out_size)
{
    const float* x   = (const float*)d_in[0];
    const float* Wg  = (const float*)d_in[1];
    const float* W1  = (const float*)d_in[2];
    const float* W2  = (const float*)d_in[3];
    const float* W3  = (const float*)d_in[4];
    const float* Ws1 = (const float*)d_in[5];
    const float* Ws2 = (const float*)d_in[6];
    const float* Ws3 = (const float*)d_in[7];
    float* out = (float*)d_out;

    cudaFuncSetAttribute(up_mma,   cudaFuncAttributeMaxDynamicSharedMemorySize, DYN_SMEM);
    cudaFuncSetAttribute(down_mma, cudaFuncAttributeMaxDynamicSharedMemorySize, DYN_SMEM);

    void *xh, *xl, *w1h, *w1l, *w3h, *w3l, *w2h, *w2l;
    void *ws1h, *ws1l, *ws3h, *ws3l, *ws2h, *ws2l;
    cudaGetSymbolAddress(&xh,  g_Xh);  cudaGetSymbolAddress(&xl,  g_Xl);
    cudaGetSymbolAddress(&w1h, g_W1h); cudaGetSymbolAddress(&w1l, g_W1l);
    cudaGetSymbolAddress(&w3h, g_W3h); cudaGetSymbolAddress(&w3l, g_W3l);
    cudaGetSymbolAddress(&w2h, g_W2h); cudaGetSymbolAddress(&w2l, g_W2l);
    cudaGetSymbolAddress(&ws1h, g_Ws1h); cudaGetSymbolAddress(&ws1l, g_Ws1l);
    cudaGetSymbolAddress(&ws3h, g_Ws3h); cudaGetSymbolAddress(&ws3l, g_Ws3l);
    cudaGetSymbolAddress(&ws2h, g_Ws2h); cudaGetSymbolAddress(&ws2l, g_Ws2l);

    // Launch order chosen so launch #6 (ncu -s 5 -c 1) is the routed-expert up GEMM.
    gate_kernel<<<T_TOK/8, 256>>>(x, Wg);                                                      // 1
    dispatch_kernel<<<E_NUM, 256>>>();                                                         // 2
    split_kernel<<<2048, 256>>>((const float4*)x,  (uint2*)xh,  (uint2*)xl,  (int)((size_t)T_TOK*D_DIM/4));        // 3
    split_kernel<<<2048, 256>>>((const float4*)W1, (uint2*)w1h, (uint2*)w1l, (int)((size_t)E_NUM*D_DIM*H_DIM/4));  // 4
    split_kernel<<<2048, 256>>>((const float4*)W3, (uint2*)w3h, (uint2*)w3l, (int)((size_t)E_NUM*D_DIM*H_DIM/4));  // 5
    up_mma  <<<dim3(CAP/BM, H_DIM/64, E_NUM), 256, DYN_SMEM>>>(H_DIM, 1);                      // 6  <- profiled
    split_kernel<<<2048, 256>>>((const float4*)W2,  (uint2*)w2h, (uint2*)w2l, (int)((size_t)E_NUM*H_DIM*D_DIM/4)); // 7
    split_kernel<<<2048, 256>>>((const float4*)Ws1, (uint2*)ws1h,(uint2*)ws1l,(int)((size_t)D_DIM*HS_DIM/4));      // 8
    split_kernel<<<2048, 256>>>((const float4*)Ws3, (uint2*)ws3h,(uint2*)ws3l,(int)((size_t)D_DIM*HS_DIM/4));      // 9
    split_kernel<<<2048, 256>>>((const float4*)Ws2, (uint2*)ws2h,(uint2*)ws2l,(int)((size_t)HS_DIM*D_DIM/4));      // 10
    up_mma  <<<dim3(T_TOK/BM, HS_DIM/64, 1), 256, DYN_SMEM>>>(HS_DIM, 0);                      // 11
    down_mma<<<dim3(T_TOK/BM, D_DIM/128, 1), 256, DYN_SMEM>>>(HS_DIM, 0, out);                 // 12 (dense init of out)
    down_mma<<<dim3(CAP/BM, D_DIM/128, E_NUM), 256, DYN_SMEM>>>(H_DIM, 1, out);                // 13 (-> pairbuf)
    combine_kernel<<<(T_TOK*D_DIM/4)/256, 256>>>(out);                                         // 14
}

// round 7
// speedup vs baseline: 1.1574x; 1.1574x over previous
#include <cuda_runtime.h>
#include <cuda_fp16.h>
#include <math.h>
#include <stdint.h>

#define T_TOK   4096
#define D_DIM   1024
#define H_DIM   512
#define HS_DIM  1024
#define E_NUM   32
#define TOPK    4
#define P_PAIRS (T_TOK*TOPK)
#define CAP     2048

#define BM 128
#define BK 32
#define STAGE_BYTES 24576
#define N_STAGE 4
#define DYN_SMEM (N_STAGE*STAGE_BYTES)   // 98304

// ---------------- scratch ----------------
__device__ int   g_pair_e[P_PAIRS];
__device__ float g_pair_w[P_PAIRS];
__device__ int   g_pair_pos[P_PAIRS];
__device__ int   g_slot_tok[E_NUM*CAP];
__device__ float g_slot_w[E_NUM*CAP];
__device__ int   g_count[E_NUM];
__device__ __align__(16) float g_pairbuf[(size_t)E_NUM*CAP*D_DIM];
__device__ __align__(16) __half g_hexp_hi[(size_t)E_NUM*CAP*H_DIM];
__device__ __align__(16) __half g_hexp_lo[(size_t)E_NUM*CAP*H_DIM];
__device__ __align__(16) __half g_hsh_hi[(size_t)T_TOK*HS_DIM];
__device__ __align__(16) __half g_hsh_lo[(size_t)T_TOK*HS_DIM];
// X split hi/lo fp16; weights single fp16 (K-major native)
__device__ __align__(16) __half g_Xh[(size_t)T_TOK*D_DIM], g_Xl[(size_t)T_TOK*D_DIM];
__device__ __align__(16) __half g_W1[(size_t)E_NUM*D_DIM*H_DIM];
__device__ __align__(16) __half g_W3[(size_t)E_NUM*D_DIM*H_DIM];
__device__ __align__(16) __half g_W2[(size_t)E_NUM*H_DIM*D_DIM];
__device__ __align__(16) __half g_Ws1[(size_t)D_DIM*HS_DIM];
__device__ __align__(16) __half g_Ws3[(size_t)D_DIM*HS_DIM];
__device__ __align__(16) __half g_Ws2[(size_t)HS_DIM*D_DIM];

// ---------------- helpers ----------------
__device__ __forceinline__ uint32_t smem_u32(const void* p) {
    return (uint32_t)__cvta_generic_to_shared(p);
}
__device__ __forceinline__ void cpa16(uint32_t dst, const void* src) {
    asm volatile("cp.async.cg.shared.global [%0], [%1], 16;" :: "r"(dst), "l"(src));
}
__device__ __forceinline__ void cpa16z(uint32_t dst, const void* src, bool valid) {
    int sz = valid ? 16 : 0;
    asm volatile("cp.async.cg.shared.global [%0], [%1], 16, %2;" :: "r"(dst), "l"(src), "r"(sz));
}
__device__ __forceinline__ void cpa_commit() { asm volatile("cp.async.commit_group;"); }
__device__ __forceinline__ void cpa_wait0()  { asm volatile("cp.async.wait_group 0;"); }
__device__ __forceinline__ void cpa_wait1()  { asm volatile("cp.async.wait_group 1;"); }
__device__ __forceinline__ void cpa_wait2()  { asm volatile("cp.async.wait_group 2;"); }
__device__ __forceinline__ void ldsm_x4(uint32_t* r, uint32_t a) {
    asm volatile("ldmatrix.sync.aligned.m8n8.x4.shared.b16 {%0,%1,%2,%3}, [%4];"
        : "=r"(r[0]), "=r"(r[1]), "=r"(r[2]), "=r"(r[3]) : "r"(a));
}
__device__ __forceinline__ void ldsm_x4_t(uint32_t* r, uint32_t a) {
    asm volatile("ldmatrix.sync.aligned.m8n8.x4.trans.shared.b16 {%0,%1,%2,%3}, [%4];"
        : "=r"(r[0]), "=r"(r[1]), "=r"(r[2]), "=r"(r[3]) : "r"(a));
}
__device__ __forceinline__ void mma16816(float* c, const uint32_t* a, const uint32_t* b) {
    asm volatile(
        "mma.sync.aligned.m16n8k16.row.col.f32.f16.f16.f32 "
        "{%0,%1,%2,%3}, {%4,%5,%6,%7}, {%8,%9}, {%0,%1,%2,%3};"
        : "+f"(c[0]), "+f"(c[1]), "+f"(c[2]), "+f"(c[3])
        : "r"(a[0]), "r"(a[1]), "r"(a[2]), "r"(a[3]), "r"(b[0]), "r"(b[1]));
}
__device__ __forceinline__ void split_h(float x, uint16_t& h, uint16_t& l) {
    __half hb = __float2half_rn(x);
    float r = x - __half2float(hb);
    __half lb = __float2half_rn(r);
    h = __half_as_ushort(hb);
    l = __half_as_ushort(lb);
}
__device__ __forceinline__ void pack4h(float4 v, uint2& hp, uint2& lp) {
    uint16_t hx,lx,hy,ly,hz,lz,hw,lw;
    split_h(v.x,hx,lx); split_h(v.y,hy,ly);
    split_h(v.z,hz,lz); split_h(v.w,hw,lw);
    hp = make_uint2((uint32_t)hx | ((uint32_t)hy<<16), (uint32_t)hz | ((uint32_t)hw<<16));
    lp = make_uint2((uint32_t)lx | ((uint32_t)ly<<16), (uint32_t)lz | ((uint32_t)lw<<16));
}
__device__ __forceinline__ uint2 conv4h(float4 v) {
    uint16_t a = __half_as_ushort(__float2half_rn(v.x));
    uint16_t b = __half_as_ushort(__float2half_rn(v.y));
    uint16_t c = __half_as_ushort(__float2half_rn(v.z));
    uint16_t d = __half_as_ushort(__float2half_rn(v.w));
    return make_uint2((uint32_t)a | ((uint32_t)b<<16), (uint32_t)c | ((uint32_t)d<<16));
}
__device__ __forceinline__ uint32_t a_off(int r, int s) {
    return (uint32_t)r*64u + (uint32_t)((s ^ ((r>>1)&3)) << 4);
}
__device__ __forceinline__ uint32_t b_off(int r, int s, int RB) {
    return (uint32_t)r*(uint32_t)RB + (uint32_t)((s ^ (r&7)) << 4);
}

// ---------------- splits / converts ----------------
__global__ __launch_bounds__(256)
void splitX_kernel(const float4* __restrict__ src, uint2* __restrict__ h,
                   uint2* __restrict__ l, int n4)
{
    for (int i = blockIdx.x*blockDim.x + threadIdx.x; i < n4; i += gridDim.x*blockDim.x) {
        uint2 hp, lp; pack4h(src[i], hp, lp);
        h[i] = hp; l[i] = lp;
    }
}
__global__ __launch_bounds__(256)
void convW_kernel(const float4* __restrict__ src, uint2* __restrict__ o, int n4)
{
    for (int i = blockIdx.x*blockDim.x + threadIdx.x; i < n4; i += gridDim.x*blockDim.x)
        o[i] = conv4h(src[i]);
}

// ---------------- gating ----------------
__global__ __launch_bounds__(256)
void gate_kernel(const float* __restrict__ X, const float* __restrict__ Wg)
{
    int warp = (blockIdx.x*blockDim.x + threadIdx.x) >> 5;
    int lane = threadIdx.x & 31;
    if (warp >= T_TOK) return;
    const float* xr = X + (size_t)warp * D_DIM;
    float xv[32];
    #pragma unroll
    for (int i = 0; i < 32; i++) xv[i] = xr[lane + 32*i];

    float mylogit = 0.f;
    #pragma unroll 1
    for (int e = 0; e < E_NUM; e++) {
        float d = 0.f;
        #pragma unroll
        for (int i = 0; i < 32; i++)
            d += xv[i] * Wg[(size_t)(lane + 32*i)*E_NUM + e];
        #pragma unroll
        for (int off = 16; off; off >>= 1) d += __shfl_xor_sync(0xffffffffu, d, off);
        if (lane == e) mylogit = d;
    }
    float m = mylogit;
    #pragma unroll
    for (int off = 16; off; off >>= 1) m = fmaxf(m, __shfl_xor_sync(0xffffffffu, m, off));
    float p = expf(mylogit - m);
    float s = p;
    #pragma unroll
    for (int off = 16; off; off >>= 1) s += __shfl_xor_sync(0xffffffffu, s, off);
    float prob = p / s;

    for (int k = 0; k < TOPK; k++) {
        float v = prob; int idx = lane;
        #pragma unroll
        for (int off = 16; off; off >>= 1) {
            float ov = __shfl_xor_sync(0xffffffffu, v, off);
            int   oi = __shfl_xor_sync(0xffffffffu, idx, off);
            if (ov > v || (ov == v && oi < idx)) { v = ov; idx = oi; }
        }
        if (lane == 0) {
            g_pair_e[warp*TOPK + k] = idx;
            g_pair_w[warp*TOPK + k] = v;
        }
        if (lane == idx) prob = -1.f;
    }
}

// ---------------- dispatch ----------------
__global__ __launch_bounds__(256)
void dispatch_kernel()
{
    int e = blockIdx.x;
    int tid = threadIdx.x;
    int lane = tid & 31, wid = tid >> 5;
    __shared__ int wtot[8];
    __shared__ int s_run;
    if (tid == 0) s_run = 0;
    __syncthreads();

    for (int base = 0; base < P_PAIRS; base += 256) {
        int p = base + tid;
        int flag = (g_pair_e[p] == e) ? 1 : 0;
        unsigned b = __ballot_sync(0xffffffffu, flag);
        int woff = __popc(b & ((1u << lane) - 1u));
        if (lane == 0) wtot[wid] = __popc(b);
        __syncthreads();
        int excl = 0, tot = 0;
        #pragma unroll
        for (int w = 0; w < 8; w++) { if (w < wid) excl += wtot[w]; tot += wtot[w]; }
        int pos = s_run + excl + woff;
        if (flag) {
            if (pos < CAP) {
                g_slot_tok[e*CAP + pos] = p >> 2;
                g_slot_w  [e*CAP + pos] = g_pair_w[p];
                g_pair_pos[p] = e*CAP + pos;
            } else {
                g_pair_pos[p] = -1;
            }
        }
        __syncthreads();
        if (tid == 0) s_run += tot;
        __syncthreads();
    }
    if (tid == 0) g_count[e] = min(s_run, CAP);
}

// ---------------- combine ----------------
__global__ __launch_bounds__(256)
void combine_kernel(float* __restrict__ out)
{
    int idx = blockIdx.x*blockDim.x + threadIdx.x;
    int t  = idx >> 8;
    int c4 = idx & 255;
    float4 acc = ((float4*)out)[idx];
    #pragma unroll
    for (int k = 0; k < TOPK; k++) {
        int pos = g_pair_pos[t*TOPK + k];
        if (pos >= 0) {
            float4 v = ((const float4*)g_pairbuf)[(size_t)pos*256 + c4];
            acc.x += v.x; acc.y += v.y; acc.z += v.z; acc.w += v.w;
        }
    }
    ((float4*)out)[idx] = acc;
}

// =====================================================================
// up: H = silu(X@W1) * (X@W3)  — fp16 2-pass, 4-stage cp.async
// block 128x64, warps 2Mx4N, warp tile 64x16
// stage: Ah 0 (8K) Al 8192 B1 16384 (4K) B3 20480 (4K) = 24576
// =====================================================================
__global__ __launch_bounds__(256, 2)
void up_mma(int NN, int expert_mode)
{
    extern __shared__ char sm[];
    uint32_t sbase = smem_u32(sm);

    int e = blockIdx.z;
    int M_eff; const int* rows = nullptr;
    const __half *B1_g, *B3_g;
    __half *Hhi, *Hlo;
    if (expert_mode) {
        M_eff = g_count[e];
        rows  = g_slot_tok + e*CAP;
        size_t wo = (size_t)e*D_DIM*H_DIM;
        B1_g = g_W1 + wo; B3_g = g_W3 + wo;
        Hhi = g_hexp_hi + (size_t)e*CAP*NN;
        Hlo = g_hexp_lo + (size_t)e*CAP*NN;
    } else {
        M_eff = T_TOK;
        B1_g = g_Ws1; B3_g = g_Ws3;
        Hhi = g_hsh_hi; Hlo = g_hsh_lo;
    }
    int mbase = blockIdx.x * BM;
    if (mbase >= M_eff) return;
    int nbase = blockIdx.y * 64;
    const int KK = D_DIM;
    const int NT = KK / BK;

    int tid = threadIdx.x, lane = tid & 31, wid = tid >> 5;
    int wm = wid >> 2, wn = wid & 3;

    int ar0 = tid >> 2, as = tid & 3;
    bool avA[2]; const __half *XhP[2], *XlP[2];
    #pragma unroll
    for (int h = 0; h < 2; h++) {
        int slot = mbase + ar0 + h*64;
        avA[h] = slot < M_eff;
        int tok = avA[h] ? (rows ? rows[slot] : slot) : 0;
        XhP[h] = g_Xh + (size_t)tok*KK + as*8;
        XlP[h] = g_Xl + (size_t)tok*KK + as*8;
    }
    int brow = tid >> 3, bs = tid & 7;

    auto load_stage = [&](int s, int kt) {
        uint32_t st = sbase + (uint32_t)s*STAGE_BYTES;
        #pragma unroll
        for (int h = 0; h < 2; h++) {
            uint32_t d = a_off(ar0 + h*64, as);
            cpa16z(st + d,        XhP[h] + kt, avA[h]);
            cpa16z(st + 8192 + d, XlP[h] + kt, avA[h]);
        }
        uint32_t d = b_off(brow, bs, 128);
        size_t src = (size_t)(kt + brow)*NN + nbase + bs*8;
        cpa16(st + 16384 + d, B1_g + src);
        cpa16(st + 20480 + d, B3_g + src);
        cpa_commit();
    };

    float c1[4][2][4] = {}, c3[4][2][4] = {};

    load_stage(0, 0);
    load_stage(1, BK);
    load_stage(2, 2*BK);
    for (int t = 0; t < NT; t++) {
        int s = t & 3;
        if (t < NT - 2) cpa_wait2(); else if (t == NT - 2) cpa_wait1(); else cpa_wait0();
        __syncthreads();
        if (t + 3 < NT) load_stage((t + 3) & 3, (t + 3) * BK);

        uint32_t st = sbase + (uint32_t)s*STAGE_BYTES;
        #pragma unroll
        for (int ks = 0; ks < 2; ks++) {
            int k0 = ks * 16;
            int rr = k0 + (lane & 7) + ((lane >> 3) & 1) * 8;
            int cc = wn*16 + (lane >> 4) * 8;
            uint32_t boff = b_off(rr, cc >> 3, 128);
            uint32_t b1[4], b3[4];
            ldsm_x4_t(b1, st + 16384 + boff);
            ldsm_x4_t(b3, st + 20480 + boff);
            #pragma unroll
            for (int mt = 0; mt < 4; mt++) {
                int r = wm*64 + mt*16 + (lane & 15);
                int sA = (k0 >> 3) + (lane >> 4);
                uint32_t aoff = a_off(r, sA);
                uint32_t ah[4], al[4];
                ldsm_x4(ah, st + aoff);
                ldsm_x4(al, st + 8192 + aoff);
                #pragma unroll
                for (int nt = 0; nt < 2; nt++) {
                    mma16816(c1[mt][nt], ah, &b1[nt*2]);
                    mma16816(c1[mt][nt], al, &b1[nt*2]);
                    mma16816(c3[mt][nt], ah, &b3[nt*2]);
                    mma16816(c3[mt][nt], al, &b3[nt*2]);
                }
            }
        }
    }

    int r0 = lane >> 2, cb = (lane & 3) * 2;
    #pragma unroll
    for (int mt = 0; mt < 4; mt++)
        #pragma unroll
        for (int nt = 0; nt < 2; nt++) {
            int n = nbase + wn*16 + nt*8 + cb;
            #pragma unroll
            for (int p = 0; p < 2; p++) {
                int m = mbase + wm*64 + mt*16 + r0 + p*8;
                if (m < M_eff) {
                    float g0 = c1[mt][nt][2*p+0], g1 = c1[mt][nt][2*p+1];
                    float v0 = g0 / (1.f + expf(-g0)) * c3[mt][nt][2*p+0];
                    float v1 = g1 / (1.f + expf(-g1)) * c3[mt][nt][2*p+1];
                    uint16_t h0,l0,h1,l1;
                    split_h(v0,h0,l0); split_h(v1,h1,l1);
                    *(uint32_t*)&Hhi[(size_t)m*NN + n] = (uint32_t)h0 | ((uint32_t)h1<<16);
                    *(uint32_t*)&Hlo[(size_t)m*NN + n] = (uint32_t)l0 | ((uint32_t)l1<<16);
                }
            }
        }
}

// =====================================================================
// down: fp16 2-pass, 4-stage cp.async; block 128x128, warps 2Mx4N
// expert: weighted rows -> g_pairbuf; shared: dense store to out
// stage: Ah 0 (8K) Al 8192 B 16384 (8K) = 24576
// =====================================================================
__global__ __launch_bounds__(256, 2)
void down_mma(int KK, int expert_mode, float* __restrict__ out)
{
    extern __shared__ char sm[];
    uint32_t sbase = smem_u32(sm);

    int e = blockIdx.z;
    int M_eff; const float* wv = nullptr;
    const __half *Ah_g, *Al_g, *B_g;
    float* obase;
    if (expert_mode) {
        M_eff = g_count[e];
        wv    = g_slot_w  + e*CAP;
        B_g   = g_W2 + (size_t)e*H_DIM*D_DIM;
        Ah_g  = g_hexp_hi + (size_t)e*CAP*KK;
        Al_g  = g_hexp_lo + (size_t)e*CAP*KK;
        obase = g_pairbuf + (size_t)e*CAP*D_DIM;
    } else {
        M_eff = T_TOK;
        B_g   = g_Ws2;
        Ah_g  = g_hsh_hi; Al_g = g_hsh_lo;
        obase = out;
    }
    int mbase = blockIdx.x * BM;
    if (mbase >= M_eff) return;
    int nbase = blockIdx.y * 128;
    const int NT = KK / BK;

    int tid = threadIdx.x, lane = tid & 31, wid = tid >> 5;
    int wm = wid >> 2, wn = wid & 3;

    int ar0 = tid >> 2, as = tid & 3;
    bool avA[2]; const __half *AhP[2], *AlP[2];
    #pragma unroll
    for (int h = 0; h < 2; h++) {
        int slot = mbase + ar0 + h*64;
        avA[h] = slot < M_eff;
        int rr = avA[h] ? slot : mbase;
        AhP[h] = Ah_g + (size_t)rr*KK + as*8;
        AlP[h] = Al_g + (size_t)rr*KK + as*8;
    }
    int br0 = tid >> 4, bs0 = tid & 15;

    auto load_stage = [&](int s, int kt) {
        uint32_t st = sbase + (uint32_t)s*STAGE_BYTES;
        #pragma unroll
        for (int h = 0; h < 2; h++) {
            uint32_t d = a_off(ar0 + h*64, as);
            cpa16z(st + d,        AhP[h] + kt, avA[h]);
            cpa16z(st + 8192 + d, AlP[h] + kt, avA[h]);
        }
        #pragma unroll
        for (int h = 0; h < 2; h++) {
            int r = br0 + h*16;
            uint32_t d = b_off(r, bs0, 256);
            cpa16(st + 16384 + d, B_g + (size_t)(kt + r)*D_DIM + nbase + bs0*8);
        }
        cpa_commit();
    };

    float c[4][4][4] = {};

    load_stage(0, 0);
    load_stage(1, BK);
    load_stage(2, 2*BK);
    for (int t = 0; t < NT; t++) {
        int s = t & 3;
        if (t < NT - 2) cpa_wait2(); else if (t == NT - 2) cpa_wait1(); else cpa_wait0();
        __syncthreads();
        if (t + 3 < NT) load_stage((t + 3) & 3, (t + 3) * BK);

        uint32_t st = sbase + (uint32_t)s*STAGE_BYTES;
        #pragma unroll
        for (int ks = 0; ks < 2; ks++) {
            int k0 = ks * 16;
            int rr = k0 + (lane & 7) + ((lane >> 3) & 1) * 8;
            uint32_t bf[2][4];
            #pragma unroll
            for (int h = 0; h < 2; h++) {
                int cc = wn*32 + h*16 + (lane >> 4) * 8;
                uint32_t boff = b_off(rr, cc >> 3, 256);
                ldsm_x4_t(bf[h], st + 16384 + boff);
            }
            #pragma unroll
            for (int mt = 0; mt < 4; mt++) {
                int r = wm*64 + mt*16 + (lane & 15);
                int sA = (k0 >> 3) + (lane >> 4);
                uint32_t aoff = a_off(r, sA);
                uint32_t ah[4], al[4];
                ldsm_x4(ah, st + aoff);
                ldsm_x4(al, st + 8192 + aoff);
                #pragma unroll
                for (int nt = 0; nt < 4; nt++) {
                    mma16816(c[mt][nt], ah, &bf[nt>>1][(nt&1)*2]);
                    mma16816(c[mt][nt], al, &bf[nt>>1][(nt&1)*2]);
                }
            }
        }
    }

    int r0 = lane >> 2, cb = (lane & 3) * 2;
    #pragma unroll
    for (int mt = 0; mt < 4; mt++) {
        #pragma unroll
        for (int p = 0; p < 2; p++) {
            int m = mbase + wm*64 + mt*16 + r0 + p*8;
            if (m >= M_eff) continue;
            float w = expert_mode ? wv[m] : 1.f;
            float* orow = obase + (size_t)m*D_DIM;
            #pragma unroll
            for (int nt = 0; nt < 4; nt++) {
                int n = nbase + wn*32 + nt*8 + cb;
                *(float2*)&orow[n] = make_float2(c[mt][nt][2*p+0] * w,
                                                 c[mt][nt][2*p+1] * w);
            }
        }
    }
}

// ---------------- host launcher ----------------
extern "C" void kernel_launch(void* const* d_in, const int* in_sizes, int n_in,
                              void* d_out, int out_size)
{
    const float* x   = (const float*)d_in[0];
    const float* Wg  = (const float*)d_in[1];
    const float* W1  = (const float*)d_in[2];
    const float* W2  = (const float*)d_in[3];
    const float* W3  = (const float*)d_in[4];
    const float* Ws1 = (const float*)d_in[5];
    const float* Ws2 = (const float*)d_in[6];
    const float* Ws3 = (const float*)d_in[7];
    float* out = (float*)d_out;

    cudaFuncSetAttribute(up_mma,   cudaFuncAttributeMaxDynamicSharedMemorySize, DYN_SMEM);
    cudaFuncSetAttribute(down_mma, cudaFuncAttributeMaxDynamicSharedMemorySize, DYN_SMEM);

    void *xh, *xl, *w1, *w3, *w2, *ws1, *ws3, *ws2;
    cudaGetSymbolAddress(&xh, g_Xh);  cudaGetSymbolAddress(&xl, g_Xl);
    cudaGetSymbolAddress(&w1, g_W1);  cudaGetSymbolAddress(&w3, g_W3);
    cudaGetSymbolAddress(&w2, g_W2);
    cudaGetSymbolAddress(&ws1, g_Ws1); cudaGetSymbolAddress(&ws3, g_Ws3);
    cudaGetSymbolAddress(&ws2, g_Ws2);

    gate_kernel<<<T_TOK/8, 256>>>(x, Wg);
    dispatch_kernel<<<E_NUM, 256>>>();
    splitX_kernel<<<2048, 256>>>((const float4*)x, (uint2*)xh, (uint2*)xl,
                                 (int)((size_t)T_TOK*D_DIM/4));
    convW_kernel<<<2048, 256>>>((const float4*)W1,  (uint2*)w1,  (int)((size_t)E_NUM*D_DIM*H_DIM/4));
    convW_kernel<<<2048, 256>>>((const float4*)W3,  (uint2*)w3,  (int)((size_t)E_NUM*D_DIM*H_DIM/4));
    up_mma  <<<dim3(CAP/BM, H_DIM/64, E_NUM), 256, DYN_SMEM>>>(H_DIM, 1);
    convW_kernel<<<2048, 256>>>((const float4*)W2,  (uint2*)w2,  (int)((size_t)E_NUM*H_DIM*D_DIM/4));
    convW_kernel<<<2048, 256>>>((const float4*)Ws1, (uint2*)ws1, (int)((size_t)D_DIM*HS_DIM/4));
    convW_kernel<<<2048, 256>>>((const float4*)Ws3, (uint2*)ws3, (int)((size_t)D_DIM*HS_DIM/4));
    convW_kernel<<<2048, 256>>>((const float4*)Ws2, (uint2*)ws2, (int)((size_t)HS_DIM*D_DIM/4));
    up_mma  <<<dim3(T_TOK/BM, HS_DIM/64, 1), 256, DYN_SMEM>>>(HS_DIM, 0);
    down_mma<<<dim3(T_TOK/BM, D_DIM/128, 1), 256, DYN_SMEM>>>(HS_DIM, 0, out);   // dense init of out
    down_mma<<<dim3(CAP/BM, D_DIM/128, E_NUM), 256, DYN_SMEM>>>(H_DIM, 1, out);  // -> pairbuf
    combine_kernel<<<(T_TOK*D_DIM/4)/256, 256>>>(out);
}

// round 8
// speedup vs baseline: 1.4260x; 1.2321x over previous
#include <cuda_runtime.h>
#include <cuda_fp16.h>
#include <math.h>
#include <stdint.h>

#define T_TOK   4096
#define D_DIM   1024
#define H_DIM   512
#define HS_DIM  1024
#define E_NUM   32
#define TOPK    4
#define P_PAIRS (T_TOK*TOPK)
#define CAP     2048

#define BM 128
#define BK 32
#define STAGE_BYTES 16384
#define N_STAGE 4
#define DYN_SMEM (N_STAGE*STAGE_BYTES)   // 65536

// ---------------- scratch ----------------
__device__ int   g_pair_e[P_PAIRS];
__device__ float g_pair_w[P_PAIRS];
__device__ int   g_pair_pos[P_PAIRS];
__device__ int   g_slot_tok[E_NUM*CAP];
__device__ float g_slot_w[E_NUM*CAP];
__device__ int   g_count[E_NUM];
__device__ __align__(16) float g_pairbuf[(size_t)E_NUM*CAP*D_DIM];
__device__ __align__(16) __half g_hexp[(size_t)E_NUM*CAP*H_DIM];
__device__ __align__(16) __half g_hsh[(size_t)T_TOK*HS_DIM];
// single fp16 operands, K-major native
__device__ __align__(16) __half g_X[(size_t)T_TOK*D_DIM];
__device__ __align__(16) __half g_W1[(size_t)E_NUM*D_DIM*H_DIM];
__device__ __align__(16) __half g_W3[(size_t)E_NUM*D_DIM*H_DIM];
__device__ __align__(16) __half g_W2[(size_t)E_NUM*H_DIM*D_DIM];
__device__ __align__(16) __half g_Ws1[(size_t)D_DIM*HS_DIM];
__device__ __align__(16) __half g_Ws3[(size_t)D_DIM*HS_DIM];
__device__ __align__(16) __half g_Ws2[(size_t)HS_DIM*D_DIM];

// ---------------- helpers ----------------
__device__ __forceinline__ uint32_t smem_u32(const void* p) {
    return (uint32_t)__cvta_generic_to_shared(p);
}
__device__ __forceinline__ void cpa16(uint32_t dst, const void* src) {
    asm volatile("cp.async.cg.shared.global [%0], [%1], 16;" :: "r"(dst), "l"(src));
}
__device__ __forceinline__ void cpa16z(uint32_t dst, const void* src, bool valid) {
    int sz = valid ? 16 : 0;
    asm volatile("cp.async.cg.shared.global [%0], [%1], 16, %2;" :: "r"(dst), "l"(src), "r"(sz));
}
__device__ __forceinline__ void cpa_commit() { asm volatile("cp.async.commit_group;"); }
__device__ __forceinline__ void cpa_wait0()  { asm volatile("cp.async.wait_group 0;"); }
__device__ __forceinline__ void cpa_wait1()  { asm volatile("cp.async.wait_group 1;"); }
__device__ __forceinline__ void cpa_wait2()  { asm volatile("cp.async.wait_group 2;"); }
__device__ __forceinline__ void ldsm_x4(uint32_t* r, uint32_t a) {
    asm volatile("ldmatrix.sync.aligned.m8n8.x4.shared.b16 {%0,%1,%2,%3}, [%4];"
        : "=r"(r[0]), "=r"(r[1]), "=r"(r[2]), "=r"(r[3]) : "r"(a));
}
__device__ __forceinline__ void ldsm_x4_t(uint32_t* r, uint32_t a) {
    asm volatile("ldmatrix.sync.aligned.m8n8.x4.trans.shared.b16 {%0,%1,%2,%3}, [%4];"
        : "=r"(r[0]), "=r"(r[1]), "=r"(r[2]), "=r"(r[3]) : "r"(a));
}
__device__ __forceinline__ void mma16816(float* c, const uint32_t* a, const uint32_t* b) {
    asm volatile(
        "mma.sync.aligned.m16n8k16.row.col.f32.f16.f16.f32 "
        "{%0,%1,%2,%3}, {%4,%5,%6,%7}, {%8,%9}, {%0,%1,%2,%3};"
        : "+f"(c[0]), "+f"(c[1]), "+f"(c[2]), "+f"(c[3])
        : "r"(a[0]), "r"(a[1]), "r"(a[2]), "r"(a[3]), "r"(b[0]), "r"(b[1]));
}
__device__ __forceinline__ uint2 conv4h(float4 v) {
    __half2 ab = __floats2half2_rn(v.x, v.y);
    __half2 cd = __floats2half2_rn(v.z, v.w);
    return make_uint2(*(uint32_t*)&ab, *(uint32_t*)&cd);
}
__device__ __forceinline__ uint32_t a_off(int r, int s) {
    return (uint32_t)r*64u + (uint32_t)((s ^ ((r>>1)&3)) << 4);
}
__device__ __forceinline__ uint32_t b_off(int r, int s, int RB) {
    return (uint32_t)r*(uint32_t)RB + (uint32_t)((s ^ (r&7)) << 4);
}

// ---------------- converts ----------------
__global__ __launch_bounds__(256)
void conv1_kernel(const float4* __restrict__ s, uint2* __restrict__ o, int n4)
{
    for (int i = blockIdx.x*blockDim.x + threadIdx.x; i < n4; i += gridDim.x*blockDim.x)
        o[i] = conv4h(s[i]);
}
__global__ __launch_bounds__(256)
void conv2_kernel(const float4* __restrict__ sA, uint2* __restrict__ oA,
                  const float4* __restrict__ sB, uint2* __restrict__ oB, int n4)
{
    for (int i = blockIdx.x*blockDim.x + threadIdx.x; i < n4; i += gridDim.x*blockDim.x) {
        oA[i] = conv4h(sA[i]);
        oB[i] = conv4h(sB[i]);
    }
}

// ---------------- gating ----------------
__global__ __launch_bounds__(256)
void gate_kernel(const float* __restrict__ X, const float* __restrict__ Wg)
{
    int warp = (blockIdx.x*blockDim.x + threadIdx.x) >> 5;
    int lane = threadIdx.x & 31;
    if (warp >= T_TOK) return;
    const float* xr = X + (size_t)warp * D_DIM;
    float xv[32];
    #pragma unroll
    for (int i = 0; i < 32; i++) xv[i] = xr[lane + 32*i];

    float mylogit = 0.f;
    #pragma unroll 1
    for (int e = 0; e < E_NUM; e++) {
        float d = 0.f;
        #pragma unroll
        for (int i = 0; i < 32; i++)
            d += xv[i] * Wg[(size_t)(lane + 32*i)*E_NUM + e];
        #pragma unroll
        for (int off = 16; off; off >>= 1) d += __shfl_xor_sync(0xffffffffu, d, off);
        if (lane == e) mylogit = d;
    }
    float m = mylogit;
    #pragma unroll
    for (int off = 16; off; off >>= 1) m = fmaxf(m, __shfl_xor_sync(0xffffffffu, m, off));
    float p = expf(mylogit - m);
    float s = p;
    #pragma unroll
    for (int off = 16; off; off >>= 1) s += __shfl_xor_sync(0xffffffffu, s, off);
    float prob = p / s;

    for (int k = 0; k < TOPK; k++) {
        float v = prob; int idx = lane;
        #pragma unroll
        for (int off = 16; off; off >>= 1) {
            float ov = __shfl_xor_sync(0xffffffffu, v, off);
            int   oi = __shfl_xor_sync(0xffffffffu, idx, off);
            if (ov > v || (ov == v && oi < idx)) { v = ov; idx = oi; }
        }
        if (lane == 0) {
            g_pair_e[warp*TOPK + k] = idx;
            g_pair_w[warp*TOPK + k] = v;
        }
        if (lane == idx) prob = -1.f;
    }
}

// ---------------- dispatch ----------------
__global__ __launch_bounds__(256)
void dispatch_kernel()
{
    int e = blockIdx.x;
    int tid = threadIdx.x;
    int lane = tid & 31, wid = tid >> 5;
    __shared__ int wtot[8];
    __shared__ int s_run;
    if (tid == 0) s_run = 0;
    __syncthreads();

    for (int base = 0; base < P_PAIRS; base += 256) {
        int p = base + tid;
        int flag = (g_pair_e[p] == e) ? 1 : 0;
        unsigned b = __ballot_sync(0xffffffffu, flag);
        int woff = __popc(b & ((1u << lane) - 1u));
        if (lane == 0) wtot[wid] = __popc(b);
        __syncthreads();
        int excl = 0, tot = 0;
        #pragma unroll
        for (int w = 0; w < 8; w++) { if (w < wid) excl += wtot[w]; tot += wtot[w]; }
        int pos = s_run + excl + woff;
        if (flag) {
            if (pos < CAP) {
                g_slot_tok[e*CAP + pos] = p >> 2;
                g_slot_w  [e*CAP + pos] = g_pair_w[p];
                g_pair_pos[p] = e*CAP + pos;
            } else {
                g_pair_pos[p] = -1;
            }
        }
        __syncthreads();
        if (tid == 0) s_run += tot;
        __syncthreads();
    }
    if (tid == 0) g_count[e] = min(s_run, CAP);
}

// ---------------- combine ----------------
__global__ __launch_bounds__(256)
void combine_kernel(float* __restrict__ out)
{
    int idx = blockIdx.x*blockDim.x + threadIdx.x;
    int t  = idx >> 8;
    int c4 = idx & 255;
    float4 acc = ((float4*)out)[idx];
    #pragma unroll
    for (int k = 0; k < TOPK; k++) {
        int pos = g_pair_pos[t*TOPK + k];
        if (pos >= 0) {
            float4 v = ((const float4*)g_pairbuf)[(size_t)pos*256 + c4];
            acc.x += v.x; acc.y += v.y; acc.z += v.z; acc.w += v.w;
        }
    }
    ((float4*)out)[idx] = acc;
}

// =====================================================================
// up: H = silu(X@W1) * (X@W3)  — fp16 1-pass, 4-stage cp.async
// block 128x64, warps 2Mx4N, warp tile 64x16
// stage: A 0 (8K) B1 8192 (4K) B3 12288 (4K) = 16K
// =====================================================================
__global__ __launch_bounds__(256, 2)
void up_mma(int NN, int expert_mode)
{
    extern __shared__ char sm[];
    uint32_t sbase = smem_u32(sm);

    int e = blockIdx.z;
    int M_eff; const int* rows = nullptr;
    const __half *B1_g, *B3_g;
    __half *Hh;
    if (expert_mode) {
        M_eff = g_count[e];
        rows  = g_slot_tok + e*CAP;
        size_t wo = (size_t)e*D_DIM*H_DIM;
        B1_g = g_W1 + wo; B3_g = g_W3 + wo;
        Hh = g_hexp + (size_t)e*CAP*NN;
    } else {
        M_eff = T_TOK;
        B1_g = g_Ws1; B3_g = g_Ws3;
        Hh = g_hsh;
    }
    int mbase = blockIdx.x * BM;
    if (mbase >= M_eff) return;
    int nbase = blockIdx.y * 64;
    const int KK = D_DIM;
    const int NT = KK / BK;

    int tid = threadIdx.x, lane = tid & 31, wid = tid >> 5;
    int wm = wid >> 2, wn = wid & 3;

    int ar0 = tid >> 2, as = tid & 3;
    bool avA[2]; const __half* XP[2];
    #pragma unroll
    for (int h = 0; h < 2; h++) {
        int slot = mbase + ar0 + h*64;
        avA[h] = slot < M_eff;
        int tok = avA[h] ? (rows ? rows[slot] : slot) : 0;
        XP[h] = g_X + (size_t)tok*KK + as*8;
    }
    int brow = tid >> 3, bs = tid & 7;

    auto load_stage = [&](int s, int kt) {
        uint32_t st = sbase + (uint32_t)s*STAGE_BYTES;
        #pragma unroll
        for (int h = 0; h < 2; h++)
            cpa16z(st + a_off(ar0 + h*64, as), XP[h] + kt, avA[h]);
        uint32_t d = b_off(brow, bs, 128);
        size_t src = (size_t)(kt + brow)*NN + nbase + bs*8;
        cpa16(st + 8192  + d, B1_g + src);
        cpa16(st + 12288 + d, B3_g + src);
        cpa_commit();
    };

    float c1[4][2][4] = {}, c3[4][2][4] = {};

    load_stage(0, 0);
    load_stage(1, BK);
    load_stage(2, 2*BK);
    for (int t = 0; t < NT; t++) {
        int s = t & 3;
        if (t < NT - 2) cpa_wait2(); else if (t == NT - 2) cpa_wait1(); else cpa_wait0();
        __syncthreads();
        if (t + 3 < NT) load_stage((t + 3) & 3, (t + 3) * BK);

        uint32_t st = sbase + (uint32_t)s*STAGE_BYTES;
        #pragma unroll
        for (int ks = 0; ks < 2; ks++) {
            int k0 = ks * 16;
            int rr = k0 + (lane & 7) + ((lane >> 3) & 1) * 8;
            int cc = wn*16 + (lane >> 4) * 8;
            uint32_t boff = b_off(rr, cc >> 3, 128);
            uint32_t b1[4], b3[4];
            ldsm_x4_t(b1, st + 8192  + boff);
            ldsm_x4_t(b3, st + 12288 + boff);
            #pragma unroll
            for (int mt = 0; mt < 4; mt++) {
                int r = wm*64 + mt*16 + (lane & 15);
                int sA = (k0 >> 3) + (lane >> 4);
                uint32_t ah[4];
                ldsm_x4(ah, st + a_off(r, sA));
                #pragma unroll
                for (int nt = 0; nt < 2; nt++) {
                    mma16816(c1[mt][nt], ah, &b1[nt*2]);
                    mma16816(c3[mt][nt], ah, &b3[nt*2]);
                }
            }
        }
    }

    int r0 = lane >> 2, cb = (lane & 3) * 2;
    #pragma unroll
    for (int mt = 0; mt < 4; mt++)
        #pragma unroll
        for (int nt = 0; nt < 2; nt++) {
            int n = nbase + wn*16 + nt*8 + cb;
            #pragma unroll
            for (int p = 0; p < 2; p++) {
                int m = mbase + wm*64 + mt*16 + r0 + p*8;
                if (m < M_eff) {
                    float g0 = c1[mt][nt][2*p+0], g1 = c1[mt][nt][2*p+1];
                    float v0 = g0 / (1.f + expf(-g0)) * c3[mt][nt][2*p+0];
                    float v1 = g1 / (1.f + expf(-g1)) * c3[mt][nt][2*p+1];
                    __half2 hv = __floats2half2_rn(v0, v1);
                    *(uint32_t*)&Hh[(size_t)m*NN + n] = *(uint32_t*)&hv;
                }
            }
        }
}

// =====================================================================
// down: fp16 1-pass, 4-stage cp.async; block 128x128, warps 2Mx4N
// expert: weighted rows -> g_pairbuf; shared: dense store to out
// stage: A 0 (8K) B 8192 (8K) = 16K
// =====================================================================
__global__ __launch_bounds__(256, 2)
void down_mma(int KK, int expert_mode, float* __restrict__ out)
{
    extern __shared__ char sm[];
    uint32_t sbase = smem_u32(sm);

    int e = blockIdx.z;
    int M_eff; const float* wv = nullptr;
    const __half *A_g, *B_g;
    float* obase;
    if (expert_mode) {
        M_eff = g_count[e];
        wv    = g_slot_w  + e*CAP;
        B_g   = g_W2 + (size_t)e*H_DIM*D_DIM;
        A_g   = g_hexp + (size_t)e*CAP*KK;
        obase = g_pairbuf + (size_t)e*CAP*D_DIM;
    } else {
        M_eff = T_TOK;
        B_g   = g_Ws2;
        A_g   = g_hsh;
        obase = out;
    }
    int mbase = blockIdx.x * BM;
    if (mbase >= M_eff) return;
    int nbase = blockIdx.y * 128;
    const int NT = KK / BK;

    int tid = threadIdx.x, lane = tid & 31, wid = tid >> 5;
    int wm = wid >> 2, wn = wid & 3;

    int ar0 = tid >> 2, as = tid & 3;
    bool avA[2]; const __half* AP[2];
    #pragma unroll
    for (int h = 0; h < 2; h++) {
        int slot = mbase + ar0 + h*64;
        avA[h] = slot < M_eff;
        int rr = avA[h] ? slot : mbase;
        AP[h] = A_g + (size_t)rr*KK + as*8;
    }
    int br0 = tid >> 4, bs0 = tid & 15;

    auto load_stage = [&](int s, int kt) {
        uint32_t st = sbase + (uint32_t)s*STAGE_BYTES;
        #pragma unroll
        for (int h = 0; h < 2; h++)
            cpa16z(st + a_off(ar0 + h*64, as), AP[h] + kt, avA[h]);
        #pragma unroll
        for (int h = 0; h < 2; h++) {
            int r = br0 + h*16;
            cpa16(st + 8192 + b_off(r, bs0, 256),
                  B_g + (size_t)(kt + r)*D_DIM + nbase + bs0*8);
        }
        cpa_commit();
    };

    float c[4][4][4] = {};

    load_stage(0, 0);
    load_stage(1, BK);
    load_stage(2, 2*BK);
    for (int t = 0; t < NT; t++) {
        int s = t & 3;
        if (t < NT - 2) cpa_wait2(); else if (t == NT - 2) cpa_wait1(); else cpa_wait0();
        __syncthreads();
        if (t + 3 < NT) load_stage((t + 3) & 3, (t + 3) * BK);

        uint32_t st = sbase + (uint32_t)s*STAGE_BYTES;
        #pragma unroll
        for (int ks = 0; ks < 2; ks++) {
            int k0 = ks * 16;
            int rr = k0 + (lane & 7) + ((lane >> 3) & 1) * 8;
            uint32_t bf[2][4];
            #pragma unroll
            for (int h = 0; h < 2; h++) {
                int cc = wn*32 + h*16 + (lane >> 4) * 8;
                ldsm_x4_t(bf[h], st + 8192 + b_off(rr, cc >> 3, 256));
            }
            #pragma unroll
            for (int mt = 0; mt < 4; mt++) {
                int r = wm*64 + mt*16 + (lane & 15);
                int sA = (k0 >> 3) + (lane >> 4);
                uint32_t ah[4];
                ldsm_x4(ah, st + a_off(r, sA));
                #pragma unroll
                for (int nt = 0; nt < 4; nt++)
                    mma16816(c[mt][nt], ah, &bf[nt>>1][(nt&1)*2]);
            }
        }
    }

    int r0 = lane >> 2, cb = (lane & 3) * 2;
    #pragma unroll
    for (int mt = 0; mt < 4; mt++) {
        #pragma unroll
        for (int p = 0; p < 2; p++) {
            int m = mbase + wm*64 + mt*16 + r0 + p*8;
            if (m >= M_eff) continue;
            float w = expert_mode ? wv[m] : 1.f;
            float* orow = obase + (size_t)m*D_DIM;
            #pragma unroll
            for (int nt = 0; nt < 4; nt++) {
                int n = nbase + wn*32 + nt*8 + cb;
                *(float2*)&orow[n] = make_float2(c[mt][nt][2*p+0] * w,
                                                 c[mt][nt][2*p+1] * w);
            }
        }
    }
}

// ---------------- host launcher ----------------
extern "C" void kernel_launch(void* const* d_in, const int* in_sizes, int n_in,
                              void* d_out, int out_size)
{
    const float* x   = (const float*)d_in[0];
    const float* Wg  = (const float*)d_in[1];
    const float* W1  = (const float*)d_in[2];
    const float* W2  = (const float*)d_in[3];
    const float* W3  = (const float*)d_in[4];
    const float* Ws1 = (const float*)d_in[5];
    const float* Ws2 = (const float*)d_in[6];
    const float* Ws3 = (const float*)d_in[7];
    float* out = (float*)d_out;

    cudaFuncSetAttribute(up_mma,   cudaFuncAttributeMaxDynamicSharedMemorySize, DYN_SMEM);
    cudaFuncSetAttribute(down_mma, cudaFuncAttributeMaxDynamicSharedMemorySize, DYN_SMEM);

    void *xp, *w1, *w3, *w2, *ws1, *ws3, *ws2;
    cudaGetSymbolAddress(&xp, g_X);
    cudaGetSymbolAddress(&w1, g_W1);  cudaGetSymbolAddress(&w3, g_W3);
    cudaGetSymbolAddress(&w2, g_W2);
    cudaGetSymbolAddress(&ws1, g_Ws1); cudaGetSymbolAddress(&ws3, g_Ws3);
    cudaGetSymbolAddress(&ws2, g_Ws2);

    // our #5 = routed-expert up_mma (harness prepends one launch; ncu -s5 captures it)
    gate_kernel<<<T_TOK/8, 256>>>(x, Wg);                                                       // 1
    dispatch_kernel<<<E_NUM, 256>>>();                                                          // 2
    conv1_kernel<<<1024, 256>>>((const float4*)x, (uint2*)xp, (int)((size_t)T_TOK*D_DIM/4));    // 3
    conv2_kernel<<<2048, 256>>>((const float4*)W1, (uint2*)w1,
                                (const float4*)W3, (uint2*)w3,
                                (int)((size_t)E_NUM*D_DIM*H_DIM/4));                            // 4
    up_mma  <<<dim3(CAP/BM, H_DIM/64, E_NUM), 256, DYN_SMEM>>>(H_DIM, 1);                       // 5 <- profiled
    conv1_kernel<<<2048, 256>>>((const float4*)W2, (uint2*)w2, (int)((size_t)E_NUM*H_DIM*D_DIM/4));
    conv2_kernel<<<1024, 256>>>((const float4*)Ws1, (uint2*)ws1,
                                (const float4*)Ws3, (uint2*)ws3,
                                (int)((size_t)D_DIM*HS_DIM/4));
    conv1_kernel<<<1024, 256>>>((const float4*)Ws2, (uint2*)ws2, (int)((size_t)HS_DIM*D_DIM/4));
    up_mma  <<<dim3(T_TOK/BM, HS_DIM/64, 1), 256, DYN_SMEM>>>(HS_DIM, 0);
    down_mma<<<dim3(T_TOK/BM, D_DIM/128, 1), 256, DYN_SMEM>>>(HS_DIM, 0, out);   // dense init
    down_mma<<<dim3(CAP/BM, D_DIM/128, E_NUM), 256, DYN_SMEM>>>(H_DIM, 1, out);  // -> pairbuf
    combine_kernel<<<(T_TOK*D_DIM/4)/256, 256>>>(out);
}